// round 4
// baseline (speedup 1.0000x reference)
#include <cuda_runtime.h>
#include <cuda_bf16.h>
#include <cstdint>

// ---------------------------------------------------------------------------
// GAT_86388972191777: 2-layer single-head GATConv (+self-loops) + linear head.
//   N = 100000 nodes, E = 3.2M edges, F_in = 256, H = 8.
// K-1: detect whether edge_index buffer is int64 or int32 (harness may downcast)
// K0: edge_index -> packed int2 (src,dst)
// K1: h1 = x@W1 (warp-per-node), a_s1/a_d1, zero accumulators
// K2: fused edge pass (no segment-max: exp arg bounded, max cancels exactly):
//     ex = exp(leaky(a_s[src]+a_d[dst])); red s[dst]+=ex; red acc[dst]+=ex*h[src]
// K3: finish layer1 (self-loop analytic) + layer2 transform
// K4: edge pass (layer 2)
// K5: finish layer2 + linear head + leaky(0.01)
// ---------------------------------------------------------------------------

#define NMAX 100000
#define EMAX 3200000

__device__ int    g_is64;            // 1 if edge_index stored as int64
__device__ int2   g_edge[EMAX];      // (src, dst) packed
__device__ float4 g_h[NMAX * 2];     // node features [N,8] as 2x float4
__device__ float  g_as[NMAX];
__device__ float  g_ad[NMAX];
__device__ float  g_s[NMAX];         // softmax denominators (excl. self-loop)
__device__ float4 g_acc[NMAX * 2];   // weighted feature accumulators

__device__ __forceinline__ float leaky02(float e) {
    return fmaxf(e, 0.2f * e);       // slope 0.2, branchless
}

// Vector reduction to global memory: red.global.add.v4.f32 (sm_90+)
__device__ __forceinline__ void red_add_f4(float4* addr, float4 v) {
    asm volatile("red.global.add.v4.f32 [%0], {%1, %2, %3, %4};"
                 :: "l"(addr), "f"(v.x), "f"(v.y), "f"(v.z), "f"(v.w)
                 : "memory");
}

// ---------- K-1: detect int64 vs int32 storage of edge_index ---------------
// int64 little-endian, values < 2^31: every odd 32-bit word is 0.
// Cross-check: int32 interpretation must yield indices in [0, N).
__global__ void k_detect(const int* __restrict__ ei32, int N) {
    if (blockIdx.x == 0 && threadIdx.x == 0) {
        int hi_all0 = 1;    // consistent with int64 layout
        int lo_ok   = 1;    // consistent with int32 layout
        for (int k = 0; k < 256; k++) {
            int lo = ei32[2 * k];
            int hi = ei32[2 * k + 1];
            if (hi != 0) hi_all0 = 0;
            if (lo < 0 || lo >= N || hi < 0 || hi >= N) lo_ok = 0;
        }
        // If high words are all zero, it's int64 (prob of 256 random int32
        // node ids all being 0 is ~0). Otherwise trust int32 if in-range.
        g_is64 = hi_all0 ? 1 : (lo_ok ? 0 : 1);
    }
}

// ---------------- K0: edge index -> packed int2 -----------------------------
__global__ void k_conv(const int* __restrict__ ei, int E) {
    int i = blockIdx.x * blockDim.x + threadIdx.x;
    if (i >= E) return;
    if (g_is64) {
        // int64 [2,E]: src low word at 2*i, dst low word at 2*E + 2*i
        g_edge[i] = make_int2(ei[2 * i], ei[2 * E + 2 * i]);
    } else {
        // int32 [2,E]: src at i, dst at E + i
        g_edge[i] = make_int2(ei[i], ei[E + i]);
    }
}

// ---------------- K1: layer-1 transform (warp per node) ---------------------
__global__ __launch_bounds__(256) void k_l1_transform(
    const float* __restrict__ x, const float* __restrict__ W1,
    const float* __restrict__ att_s, const float* __restrict__ att_d, int N)
{
    __shared__ float Wt[8 * 256];    // W1 transposed: Wt[j*256 + k]
    __shared__ float s_att[16];
    for (int i = threadIdx.x; i < 2048; i += blockDim.x) {
        int k = i >> 3, j = i & 7;
        Wt[j * 256 + k] = W1[i];
    }
    if (threadIdx.x < 8)  s_att[threadIdx.x] = att_s[threadIdx.x];
    if (threadIdx.x >= 8 && threadIdx.x < 16) s_att[threadIdx.x] = att_d[threadIdx.x - 8];
    __syncthreads();

    int warp = (blockIdx.x * blockDim.x + threadIdx.x) >> 5;
    int lane = threadIdx.x & 31;
    if (warp >= N) return;

    const float* xr = x + (size_t)warp * 256;
    float acc[8];
    #pragma unroll
    for (int j = 0; j < 8; j++) acc[j] = 0.f;

    #pragma unroll
    for (int t = 0; t < 8; t++) {
        float xv = xr[lane + 32 * t];
        #pragma unroll
        for (int j = 0; j < 8; j++)
            acc[j] = fmaf(xv, Wt[j * 256 + lane + 32 * t], acc[j]);
    }
    #pragma unroll
    for (int off = 16; off > 0; off >>= 1) {
        #pragma unroll
        for (int j = 0; j < 8; j++)
            acc[j] += __shfl_xor_sync(0xffffffffu, acc[j], off);
    }
    if (lane == 0) {
        g_h[2 * warp]     = make_float4(acc[0], acc[1], acc[2], acc[3]);
        g_h[2 * warp + 1] = make_float4(acc[4], acc[5], acc[6], acc[7]);
        float as = 0.f, ad = 0.f;
        #pragma unroll
        for (int j = 0; j < 8; j++) {
            as = fmaf(acc[j], s_att[j], as);
            ad = fmaf(acc[j], s_att[8 + j], ad);
        }
        g_as[warp] = as;
        g_ad[warp] = ad;
        g_s[warp]  = 0.f;
        float4 z = make_float4(0.f, 0.f, 0.f, 0.f);
        g_acc[2 * warp]     = z;
        g_acc[2 * warp + 1] = z;
    }
}

// ---------------- K2/K4: fused edge softmax-aggregate pass ------------------
__global__ __launch_bounds__(256) void k_edge(int E) {
    int stride = gridDim.x * blockDim.x;
    for (int i = blockIdx.x * blockDim.x + threadIdx.x; i < E; i += stride) {
        int2 sd = g_edge[i];
        int s = sd.x, d = sd.y;
        float e  = leaky02(g_as[s] + g_ad[d]);
        float ex = __expf(e);
        atomicAdd(&g_s[d], ex);
        float4 h0 = g_h[2 * s];
        float4 h1 = g_h[2 * s + 1];
        h0.x *= ex; h0.y *= ex; h0.z *= ex; h0.w *= ex;
        h1.x *= ex; h1.y *= ex; h1.z *= ex; h1.w *= ex;
        red_add_f4(&g_acc[2 * d],     h0);
        red_add_f4(&g_acc[2 * d + 1], h1);
    }
}

// ---------------- K3: finish layer1 + layer2 transform ----------------------
__global__ __launch_bounds__(256) void k_mid(
    const float* __restrict__ W2, const float* __restrict__ att_s2,
    const float* __restrict__ att_d2, const float* __restrict__ b1, int N)
{
    __shared__ float sW2[64], satts[8], sattd[8], sb1[8];
    if (threadIdx.x < 64) sW2[threadIdx.x] = W2[threadIdx.x];
    if (threadIdx.x < 8) {
        satts[threadIdx.x] = att_s2[threadIdx.x];
        sattd[threadIdx.x] = att_d2[threadIdx.x];
        sb1[threadIdx.x]   = b1[threadIdx.x];
    }
    __syncthreads();
    int i = blockIdx.x * blockDim.x + threadIdx.x;
    if (i >= N) return;

    float4 a0 = g_acc[2 * i], a1 = g_acc[2 * i + 1];
    float4 h0 = g_h[2 * i],   h1 = g_h[2 * i + 1];
    float hv[8] = {h0.x, h0.y, h0.z, h0.w, h1.x, h1.y, h1.z, h1.w};
    float av[8] = {a0.x, a0.y, a0.z, a0.w, a1.x, a1.y, a1.z, a1.w};

    float ex  = __expf(leaky02(g_as[i] + g_ad[i]));   // self-loop term
    float inv = 1.0f / (g_s[i] + ex);

    float x1v[8];
    #pragma unroll
    for (int j = 0; j < 8; j++)
        x1v[j] = fmaf(ex, hv[j], av[j]) * inv + sb1[j];

    float h2[8];
    #pragma unroll
    for (int j = 0; j < 8; j++) {
        float acc = 0.f;
        #pragma unroll
        for (int k = 0; k < 8; k++)
            acc = fmaf(x1v[k], sW2[k * 8 + j], acc);
        h2[j] = acc;
    }
    float as = 0.f, ad = 0.f;
    #pragma unroll
    for (int j = 0; j < 8; j++) {
        as = fmaf(h2[j], satts[j], as);
        ad = fmaf(h2[j], sattd[j], ad);
    }
    g_h[2 * i]     = make_float4(h2[0], h2[1], h2[2], h2[3]);
    g_h[2 * i + 1] = make_float4(h2[4], h2[5], h2[6], h2[7]);
    g_as[i] = as;
    g_ad[i] = ad;
    g_s[i]  = 0.f;
    float4 z = make_float4(0.f, 0.f, 0.f, 0.f);
    g_acc[2 * i]     = z;
    g_acc[2 * i + 1] = z;
}

// ---------------- K5: finish layer2 + linear head ---------------------------
__global__ __launch_bounds__(256) void k_fin(
    const float* __restrict__ b2, const float* __restrict__ W_lin,
    const float* __restrict__ b_lin, float* __restrict__ out, int N)
{
    __shared__ float sWl[8], sb2[8], sbl;
    if (threadIdx.x < 8) {
        sWl[threadIdx.x] = W_lin[threadIdx.x];
        sb2[threadIdx.x] = b2[threadIdx.x];
    }
    if (threadIdx.x == 0) sbl = b_lin[0];
    __syncthreads();
    int i = blockIdx.x * blockDim.x + threadIdx.x;
    if (i >= N) return;

    float4 a0 = g_acc[2 * i], a1 = g_acc[2 * i + 1];
    float4 h0 = g_h[2 * i],   h1 = g_h[2 * i + 1];
    float hv[8] = {h0.x, h0.y, h0.z, h0.w, h1.x, h1.y, h1.z, h1.w};
    float av[8] = {a0.x, a0.y, a0.z, a0.w, a1.x, a1.y, a1.z, a1.w};

    float ex  = __expf(leaky02(g_as[i] + g_ad[i]));
    float inv = 1.0f / (g_s[i] + ex);

    float o = sbl;
    #pragma unroll
    for (int j = 0; j < 8; j++) {
        float x2 = fmaf(ex, hv[j], av[j]) * inv + sb2[j];
        o = fmaf(x2, sWl[j], o);
    }
    out[i] = fmaxf(o, 0.01f * o);   // leaky(0.01)
}

// ---------------------------------------------------------------------------
extern "C" void kernel_launch(void* const* d_in, const int* in_sizes, int n_in,
                              void* d_out, int out_size) {
    const float* x   = (const float*)d_in[0];
    const int*   ei  = (const int*)d_in[1];   // int32 or int64 — detected on device
    // d_in[2] edge_type, d_in[3] edge_time: unused by the forward pass
    const float* W1  = (const float*)d_in[4];
    const float* as1 = (const float*)d_in[5];
    const float* ad1 = (const float*)d_in[6];
    const float* b1  = (const float*)d_in[7];
    const float* W2  = (const float*)d_in[8];
    const float* as2 = (const float*)d_in[9];
    const float* ad2 = (const float*)d_in[10];
    const float* b2  = (const float*)d_in[11];
    const float* Wl  = (const float*)d_in[12];
    const float* bl  = (const float*)d_in[13];
    float* out = (float*)d_out;

    int N = in_sizes[0] / 256;
    int E = in_sizes[1] / 2;
    if (N > NMAX) N = NMAX;
    if (E > EMAX) E = EMAX;

    int eb = (E + 255) / 256;
    int nb = (N + 255) / 256;
    int wb = (N + 7) / 8;            // warp-per-node, 8 warps/block
    int edge_grid = 148 * 16;        // ~1 wave of grid-stride blocks

    k_detect<<<1, 32>>>(ei, N);
    k_conv<<<eb, 256>>>(ei, E);
    k_l1_transform<<<wb, 256>>>(x, W1, as1, ad1, N);
    k_edge<<<edge_grid, 256>>>(E);
    k_mid<<<nb, 256>>>(W2, as2, ad2, b1, N);
    k_edge<<<edge_grid, 256>>>(E);
    k_fin<<<nb, 256>>>(b2, Wl, bl, out, N);
}

// round 5
// speedup vs baseline: 1.0057x; 1.0057x over previous
#include <cuda_runtime.h>
#include <cuda_bf16.h>
#include <cstdint>

// ---------------------------------------------------------------------------
// GAT_86388972191777: 2-layer single-head GATConv (+self-loops) + linear head.
//   N = 100000, E = 3.2M, F_in = 256, H = 8.
// v5: counting-sort edges by dst once; edge pass uses warp-segmented reduction
//     so only segment heads issue global REDs (dst-side L2 sectors ~0).
// ---------------------------------------------------------------------------

#define NMAX 100000
#define EMAX 3200000
#define SCAN_B 512                    // scan block width

__device__ int    g_is64;             // 1 if edge_index stored as int64
__device__ int2   g_edge[EMAX];       // (src,dst) unsorted
__device__ int2   g_sorted[EMAX];     // (src,dst) sorted by dst
__device__ int    g_cnt[NMAX];        // per-dst degree (histogram)
__device__ int    g_pos[NMAX];        // exclusive offsets -> scatter cursor
__device__ int    g_bsum[(NMAX + SCAN_B - 1) / SCAN_B];
__device__ float4 g_h[NMAX * 2];      // node features [N,8] as 2x float4
__device__ float  g_as[NMAX];
__device__ float  g_ad[NMAX];
__device__ float  g_s[NMAX];          // softmax denominators (excl. self-loop)
__device__ float4 g_acc[NMAX * 2];    // weighted feature accumulators

__device__ __forceinline__ float leaky02(float e) {
    return fmaxf(e, 0.2f * e);        // slope 0.2, branchless
}

__device__ __forceinline__ void red_add_f4(float4* addr, float4 v) {
    asm volatile("red.global.add.v4.f32 [%0], {%1, %2, %3, %4};"
                 :: "l"(addr), "f"(v.x), "f"(v.y), "f"(v.z), "f"(v.w)
                 : "memory");
}

// ---------- detect int64 vs int32 storage of edge_index ---------------------
__global__ void k_detect(const int* __restrict__ ei32, int N) {
    if (blockIdx.x == 0 && threadIdx.x == 0) {
        int hi_all0 = 1, lo_ok = 1;
        for (int k = 0; k < 256; k++) {
            int lo = ei32[2 * k];
            int hi = ei32[2 * k + 1];
            if (hi != 0) hi_all0 = 0;
            if (lo < 0 || lo >= N || hi < 0 || hi >= N) lo_ok = 0;
        }
        g_is64 = hi_all0 ? 1 : (lo_ok ? 0 : 1);
    }
}

// ---------- zero histogram ---------------------------------------------------
__global__ void k_zero(int N) {
    int i = blockIdx.x * blockDim.x + threadIdx.x;
    if (i < N) g_cnt[i] = 0;
}

// ---------- convert + histogram ---------------------------------------------
__global__ void k_conv_hist(const int* __restrict__ ei, int E) {
    int i = blockIdx.x * blockDim.x + threadIdx.x;
    if (i >= E) return;
    int2 sd;
    if (g_is64) sd = make_int2(ei[2 * i], ei[2 * E + 2 * i]);
    else        sd = make_int2(ei[i],     ei[E + i]);
    g_edge[i] = sd;
    atomicAdd(&g_cnt[sd.y], 1);
}

// ---------- 3-kernel exclusive scan over g_cnt -> g_pos ----------------------
__global__ void k_scan_a(int N) {
    __shared__ int sm[SCAN_B];
    int t = threadIdx.x, i = blockIdx.x * SCAN_B + t;
    int v = (i < N) ? g_cnt[i] : 0;
    sm[t] = v; __syncthreads();
    for (int off = 1; off < SCAN_B; off <<= 1) {
        int u = (t >= off) ? sm[t - off] : 0;
        __syncthreads();
        sm[t] += u;
        __syncthreads();
    }
    if (i < N) g_pos[i] = sm[t] - v;                 // exclusive within block
    if (t == SCAN_B - 1) g_bsum[blockIdx.x] = sm[t]; // block total
}
__global__ void k_scan_b(int NB) {
    __shared__ int sm[SCAN_B];
    int t = threadIdx.x;
    int v = (t < NB) ? g_bsum[t] : 0;
    sm[t] = v; __syncthreads();
    for (int off = 1; off < SCAN_B; off <<= 1) {
        int u = (t >= off) ? sm[t - off] : 0;
        __syncthreads();
        sm[t] += u;
        __syncthreads();
    }
    if (t < NB) g_bsum[t] = sm[t] - v;               // exclusive block offsets
}
__global__ void k_scan_c(int N) {
    int i = blockIdx.x * blockDim.x + threadIdx.x;
    if (i < N) g_pos[i] += g_bsum[i / SCAN_B];
}

// ---------- scatter into dst-sorted order -----------------------------------
__global__ void k_scatter(int E) {
    int i = blockIdx.x * blockDim.x + threadIdx.x;
    if (i >= E) return;
    int2 sd = g_edge[i];
    int p = atomicAdd(&g_pos[sd.y], 1);
    g_sorted[p] = sd;
}

// ---------- layer-1 transform (warp per node) --------------------------------
__global__ __launch_bounds__(256) void k_l1_transform(
    const float* __restrict__ x, const float* __restrict__ W1,
    const float* __restrict__ att_s, const float* __restrict__ att_d, int N)
{
    __shared__ float Wt[8 * 256];     // W1 transposed: Wt[j*256 + k]
    __shared__ float s_att[16];
    for (int i = threadIdx.x; i < 2048; i += blockDim.x) {
        int k = i >> 3, j = i & 7;
        Wt[j * 256 + k] = W1[i];
    }
    if (threadIdx.x < 8)  s_att[threadIdx.x] = att_s[threadIdx.x];
    if (threadIdx.x >= 8 && threadIdx.x < 16) s_att[threadIdx.x] = att_d[threadIdx.x - 8];
    __syncthreads();

    int warp = (blockIdx.x * blockDim.x + threadIdx.x) >> 5;
    int lane = threadIdx.x & 31;
    if (warp >= N) return;

    const float* xr = x + (size_t)warp * 256;
    float acc[8];
    #pragma unroll
    for (int j = 0; j < 8; j++) acc[j] = 0.f;
    #pragma unroll
    for (int t = 0; t < 8; t++) {
        float xv = xr[lane + 32 * t];
        #pragma unroll
        for (int j = 0; j < 8; j++)
            acc[j] = fmaf(xv, Wt[j * 256 + lane + 32 * t], acc[j]);
    }
    #pragma unroll
    for (int off = 16; off > 0; off >>= 1) {
        #pragma unroll
        for (int j = 0; j < 8; j++)
            acc[j] += __shfl_xor_sync(0xffffffffu, acc[j], off);
    }
    if (lane == 0) {
        g_h[2 * warp]     = make_float4(acc[0], acc[1], acc[2], acc[3]);
        g_h[2 * warp + 1] = make_float4(acc[4], acc[5], acc[6], acc[7]);
        float as = 0.f, ad = 0.f;
        #pragma unroll
        for (int j = 0; j < 8; j++) {
            as = fmaf(acc[j], s_att[j], as);
            ad = fmaf(acc[j], s_att[8 + j], ad);
        }
        g_as[warp] = as;
        g_ad[warp] = ad;
        g_s[warp]  = 0.f;
        float4 z = make_float4(0.f, 0.f, 0.f, 0.f);
        g_acc[2 * warp]     = z;
        g_acc[2 * warp + 1] = z;
    }
}

// ---------- edge pass over dst-sorted edges, warp-segmented reduction --------
__global__ __launch_bounds__(256) void k_edge_sorted(int E) {
    int lane  = threadIdx.x & 31;
    int warp  = (blockIdx.x * blockDim.x + threadIdx.x) >> 5;
    int nwarp = (gridDim.x * blockDim.x) >> 5;

    for (int base = warp * 32; base < E; base += nwarp * 32) {
        int i = base + lane;
        bool active = (i < E);
        int2 sd = active ? g_sorted[i] : make_int2(0, -1 - lane); // unique dummies
        int s = sd.x, d = sd.y;

        float v[9];
        #pragma unroll
        for (int j = 0; j < 9; j++) v[j] = 0.f;
        if (active) {
            float ex = __expf(leaky02(g_as[s] + g_ad[d]));
            float4 h0 = g_h[2 * s];
            float4 h1 = g_h[2 * s + 1];
            v[0] = ex * h0.x; v[1] = ex * h0.y; v[2] = ex * h0.z; v[3] = ex * h0.w;
            v[4] = ex * h1.x; v[5] = ex * h1.y; v[6] = ex * h1.z; v[7] = ex * h1.w;
            v[8] = ex;
        }

        // Segment heads: lane 0 or dst differs from previous lane
        int dprev = __shfl_up_sync(0xffffffffu, d, 1);
        bool head = (lane == 0) || (d != dprev);
        unsigned hb = __ballot_sync(0xffffffffu, head);
        // First head strictly above this lane bounds the segment
        unsigned above = hb & ~((2u << lane) - 1u);   // lane=31: 2u<<31 == 0 -> above = 0
        int segend = above ? (__ffs(above) - 1) : 32;

        // Segmented tree reduction: v[lane] accumulates [lane, segend)
        #pragma unroll
        for (int off = 1; off < 32; off <<= 1) {
            #pragma unroll
            for (int j = 0; j < 9; j++) {
                float o = __shfl_down_sync(0xffffffffu, v[j], off);
                if (lane + off < segend) v[j] += o;
            }
        }

        if (head && active) {
            atomicAdd(&g_s[d], v[8]);
            red_add_f4(&g_acc[2 * d],     make_float4(v[0], v[1], v[2], v[3]));
            red_add_f4(&g_acc[2 * d + 1], make_float4(v[4], v[5], v[6], v[7]));
        }
    }
}

// ---------- finish layer1 + layer2 transform ---------------------------------
__global__ __launch_bounds__(256) void k_mid(
    const float* __restrict__ W2, const float* __restrict__ att_s2,
    const float* __restrict__ att_d2, const float* __restrict__ b1, int N)
{
    __shared__ float sW2[64], satts[8], sattd[8], sb1[8];
    if (threadIdx.x < 64) sW2[threadIdx.x] = W2[threadIdx.x];
    if (threadIdx.x < 8) {
        satts[threadIdx.x] = att_s2[threadIdx.x];
        sattd[threadIdx.x] = att_d2[threadIdx.x];
        sb1[threadIdx.x]   = b1[threadIdx.x];
    }
    __syncthreads();
    int i = blockIdx.x * blockDim.x + threadIdx.x;
    if (i >= N) return;

    float4 a0 = g_acc[2 * i], a1 = g_acc[2 * i + 1];
    float4 h0 = g_h[2 * i],   h1 = g_h[2 * i + 1];
    float hv[8] = {h0.x, h0.y, h0.z, h0.w, h1.x, h1.y, h1.z, h1.w};
    float av[8] = {a0.x, a0.y, a0.z, a0.w, a1.x, a1.y, a1.z, a1.w};

    float ex  = __expf(leaky02(g_as[i] + g_ad[i]));   // self-loop term
    float inv = 1.0f / (g_s[i] + ex);

    float x1v[8];
    #pragma unroll
    for (int j = 0; j < 8; j++)
        x1v[j] = fmaf(ex, hv[j], av[j]) * inv + sb1[j];

    float h2[8];
    #pragma unroll
    for (int j = 0; j < 8; j++) {
        float acc = 0.f;
        #pragma unroll
        for (int k = 0; k < 8; k++)
            acc = fmaf(x1v[k], sW2[k * 8 + j], acc);
        h2[j] = acc;
    }
    float as = 0.f, ad = 0.f;
    #pragma unroll
    for (int j = 0; j < 8; j++) {
        as = fmaf(h2[j], satts[j], as);
        ad = fmaf(h2[j], sattd[j], ad);
    }
    g_h[2 * i]     = make_float4(h2[0], h2[1], h2[2], h2[3]);
    g_h[2 * i + 1] = make_float4(h2[4], h2[5], h2[6], h2[7]);
    g_as[i] = as;
    g_ad[i] = ad;
    g_s[i]  = 0.f;
    float4 z = make_float4(0.f, 0.f, 0.f, 0.f);
    g_acc[2 * i]     = z;
    g_acc[2 * i + 1] = z;
}

// ---------- finish layer2 + linear head --------------------------------------
__global__ __launch_bounds__(256) void k_fin(
    const float* __restrict__ b2, const float* __restrict__ W_lin,
    const float* __restrict__ b_lin, float* __restrict__ out, int N)
{
    __shared__ float sWl[8], sb2[8], sbl;
    if (threadIdx.x < 8) {
        sWl[threadIdx.x] = W_lin[threadIdx.x];
        sb2[threadIdx.x] = b2[threadIdx.x];
    }
    if (threadIdx.x == 0) sbl = b_lin[0];
    __syncthreads();
    int i = blockIdx.x * blockDim.x + threadIdx.x;
    if (i >= N) return;

    float4 a0 = g_acc[2 * i], a1 = g_acc[2 * i + 1];
    float4 h0 = g_h[2 * i],   h1 = g_h[2 * i + 1];
    float hv[8] = {h0.x, h0.y, h0.z, h0.w, h1.x, h1.y, h1.z, h1.w};
    float av[8] = {a0.x, a0.y, a0.z, a0.w, a1.x, a1.y, a1.z, a1.w};

    float ex  = __expf(leaky02(g_as[i] + g_ad[i]));
    float inv = 1.0f / (g_s[i] + ex);

    float o = sbl;
    #pragma unroll
    for (int j = 0; j < 8; j++) {
        float x2 = fmaf(ex, hv[j], av[j]) * inv + sb2[j];
        o = fmaf(x2, sWl[j], o);
    }
    out[i] = fmaxf(o, 0.01f * o);   // leaky(0.01)
}

// ---------------------------------------------------------------------------
extern "C" void kernel_launch(void* const* d_in, const int* in_sizes, int n_in,
                              void* d_out, int out_size) {
    const float* x   = (const float*)d_in[0];
    const int*   ei  = (const int*)d_in[1];   // layout detected on device
    const float* W1  = (const float*)d_in[4];
    const float* as1 = (const float*)d_in[5];
    const float* ad1 = (const float*)d_in[6];
    const float* b1  = (const float*)d_in[7];
    const float* W2  = (const float*)d_in[8];
    const float* as2 = (const float*)d_in[9];
    const float* ad2 = (const float*)d_in[10];
    const float* b2  = (const float*)d_in[11];
    const float* Wl  = (const float*)d_in[12];
    const float* bl  = (const float*)d_in[13];
    float* out = (float*)d_out;

    int N = in_sizes[0] / 256;
    int E = in_sizes[1] / 2;
    if (N > NMAX) N = NMAX;
    if (E > EMAX) E = EMAX;

    int eb = (E + 255) / 256;
    int nb = (N + 255) / 256;
    int wb = (N + 7) / 8;              // warp-per-node, 8 warps/block
    int NB = (N + SCAN_B - 1) / SCAN_B;
    int edge_grid = 148 * 8;           // grid-stride edge pass

    k_detect<<<1, 32>>>(ei, N);
    k_zero<<<nb, 256>>>(N);
    k_conv_hist<<<eb, 256>>>(ei, E);
    k_scan_a<<<NB, SCAN_B>>>(N);
    k_scan_b<<<1, SCAN_B>>>(NB);
    k_scan_c<<<nb, 256>>>(N);
    k_scatter<<<eb, 256>>>(E);

    k_l1_transform<<<wb, 256>>>(x, W1, as1, ad1, N);
    k_edge_sorted<<<edge_grid, 256>>>(E);
    k_mid<<<nb, 256>>>(W2, as2, ad2, b1, N);
    k_edge_sorted<<<edge_grid, 256>>>(E);
    k_fin<<<nb, 256>>>(b2, Wl, bl, out, N);
}